// round 15
// baseline (speedup 1.0000x reference)
#include <cuda_runtime.h>
#include <cuda_bf16.h>
#include <math.h>
#include <stdint.h>

#define BBATCH 4
#define NTOK 2048
#define DDIM 512
#define HHEADS 8
#define DHD 64
#define M_ROWS (BBATCH*NTOK)       // 8192
#define QKV_COLS (3*HHEADS*DHD)    // 1536
#define BHN (BBATCH*HHEADS*NTOK)   // 65536
#define CBR 0.18033688011112043f   // scale * log2e
#define C2R 0.36067376022224085f   // 2 * scale * log2e

// ---------------- scratch (device globals; no allocation allowed) ----------
__device__ __align__(16) __nv_bfloat16 g_xb[(size_t)M_ROWS*DDIM];
__device__ __align__(16) __nv_bfloat16 g_wqkvb[(size_t)QKV_COLS*DDIM];
__device__ __align__(16) __nv_bfloat16 g_woutb[(size_t)DDIM*DDIM];
__device__ __align__(16) __nv_bfloat16 g_Qb[(size_t)BHN*DHD];
__device__ __align__(16) __nv_bfloat16 g_Kb[(size_t)BHN*DHD];
__device__ __align__(16) __nv_bfloat16 g_Vb[(size_t)BHN*DHD];
__device__ __align__(16) __nv_bfloat16 g_Ob[(size_t)M_ROWS*DDIM];
__device__ float g_xsq[M_ROWS];
__device__ float g_osq[M_ROWS];
__device__ float g_wqkvsq[QKV_COLS];
__device__ float g_woutsq[DDIM];
__device__ float g_qsq[BHN];   // pre-scaled by CBR
__device__ float g_ksq[BHN];   // pre-scaled by CBR

// ---------------- small helpers -------------------------------------------
__device__ __forceinline__ uint32_t smem_u32(const void* p) {
    return (uint32_t)__cvta_generic_to_shared(p);
}
__device__ __forceinline__ void cpasync16(uint32_t dst, const void* src) {
    asm volatile("cp.async.ca.shared.global [%0], [%1], 16;" :: "r"(dst), "l"(src));
}
__device__ __forceinline__ void cp_commit() { asm volatile("cp.async.commit_group;"); }
template<int N> __device__ __forceinline__ void cp_wait() {
    asm volatile("cp.async.wait_group %0;" :: "n"(N));
}
__device__ __forceinline__ void ldm_x4(uint32_t& a0, uint32_t& a1, uint32_t& a2, uint32_t& a3, uint32_t addr) {
    asm volatile("ldmatrix.sync.aligned.m8n8.x4.shared.b16 {%0,%1,%2,%3}, [%4];"
        : "=r"(a0), "=r"(a1), "=r"(a2), "=r"(a3) : "r"(addr));
}
__device__ __forceinline__ void ldm_x4_t(uint32_t& a0, uint32_t& a1, uint32_t& a2, uint32_t& a3, uint32_t addr) {
    asm volatile("ldmatrix.sync.aligned.m8n8.x4.trans.shared.b16 {%0,%1,%2,%3}, [%4];"
        : "=r"(a0), "=r"(a1), "=r"(a2), "=r"(a3) : "r"(addr));
}
__device__ __forceinline__ void mma_bf16(float& c0, float& c1, float& c2, float& c3,
    uint32_t a0, uint32_t a1, uint32_t a2, uint32_t a3, uint32_t b0, uint32_t b1) {
    asm volatile("mma.sync.aligned.m16n8k16.row.col.f32.bf16.bf16.f32 "
        "{%0,%1,%2,%3}, {%4,%5,%6,%7}, {%8,%9}, {%0,%1,%2,%3};"
        : "+f"(c0), "+f"(c1), "+f"(c2), "+f"(c3)
        : "r"(a0), "r"(a1), "r"(a2), "r"(a3), "r"(b0), "r"(b1));
}
// pack two fp32 -> bf16x2 (PROVEN path)
__device__ __forceinline__ uint32_t pack_bf16x2(float lo, float hi) {
    uint16_t l = __bfloat16_as_ushort(__float2bfloat16_rn(lo));
    uint16_t h = __bfloat16_as_ushort(__float2bfloat16_rn(hi));
    return (uint32_t)l | ((uint32_t)h << 16);
}

// scalar exp2, no cvt-pipe ops (PROVEN in rounds 7-10). x in [-100, 0].
__device__ __forceinline__ float exp2_fast(float x) {
    x = fmaxf(x, -100.f);
    float t  = x + 12582912.0f;
    float fi = t - 12582912.0f;
    float f  = x - fi;
    int ebits = (__float_as_int(t) + (127 - 0x4B400000)) << 23;
    float p = fmaf(0.0096181291f, f, 0.0555041087f);
    p = fmaf(p, f, 0.2402264923f);
    p = fmaf(p, f, 0.6931471806f);
    p = fmaf(p, f, 1.0f);
    return __int_as_float(ebits) * p;
}

// ---------------- fused fp32->bf16 convert + row sum-of-squares (merged) ---
__global__ void cvt_rowsq_all(const float* __restrict__ x,
                              const float* __restrict__ wqkv,
                              const float* __restrict__ wout)
{
    int gid = blockIdx.x * (blockDim.x >> 5) + (threadIdx.x >> 5);
    int lane = threadIdx.x & 31;
    const float* s; __nv_bfloat16* d; float* dst; int row;
    if (gid < M_ROWS)                  { s = x;    d = g_xb;    dst = g_xsq;    row = gid; }
    else if (gid < M_ROWS + QKV_COLS)  { s = wqkv; d = g_wqkvb; dst = g_wqkvsq; row = gid - M_ROWS; }
    else                               { s = wout; d = g_woutb; dst = g_woutsq; row = gid - M_ROWS - QKV_COLS; }
    const float4* src4 = (const float4*)(s + (size_t)row * 512);
    __nv_bfloat162* d2 = (__nv_bfloat162*)(d + (size_t)row * 512);
    float sum = 0.f;
    #pragma unroll
    for (int it = 0; it < 4; it++) {
        int i = it * 32 + lane;
        float4 v = src4[i];
        __nv_bfloat162 p0 = __floats2bfloat162_rn(v.x, v.y);
        __nv_bfloat162 p1 = __floats2bfloat162_rn(v.z, v.w);
        d2[i * 2]     = p0;
        d2[i * 2 + 1] = p1;
        float2 f0 = __bfloat1622float2(p0);
        float2 f1 = __bfloat1622float2(p1);
        sum += f0.x*f0.x + f0.y*f0.y + f1.x*f1.x + f1.y*f1.y;
    }
    #pragma unroll
    for (int o = 16; o > 0; o >>= 1) sum += __shfl_xor_sync(0xffffffffu, sum, o);
    if (lane == 0) dst[row] = sum;
}

// row sum-of-squares of g_Ob (bf16) -> g_osq
__global__ void rowsq_o()
{
    int row = blockIdx.x * (blockDim.x >> 5) + (threadIdx.x >> 5);
    int lane = threadIdx.x & 31;
    const __nv_bfloat162* r2 = (const __nv_bfloat162*)(g_Ob + (size_t)row * 512);
    float sum = 0.f;
    #pragma unroll
    for (int i = lane; i < 256; i += 32) {
        float2 v = __bfloat1622float2(r2[i]);
        sum += v.x * v.x + v.y * v.y;
    }
    #pragma unroll
    for (int o = 16; o > 0; o >>= 1) sum += __shfl_xor_sync(0xffffffffu, sum, o);
    if (lane == 0) g_osq[row] = sum;
}

// ---------------- distance GEMM via bf16 mma.sync (3-stage pipeline) -------
// C[m,n] = sqrt(relu(asq[m] + bsq[n] - 2 * A[m,:]·B[n,:]))
// mode 0: scatter bf16 Q/K/V + fused CBR-scaled qsq/ksq; mode 1: fp32 Cout.
__global__ __launch_bounds__(256, 2) void dist_gemm_mma(float* __restrict__ Cout, int mode)
{
    const __nv_bfloat16* A = mode ? g_Ob : g_xb;
    const __nv_bfloat16* B = mode ? g_woutb : g_wqkvb;
    const float* asq = mode ? g_osq : g_xsq;
    const float* bsq = mode ? g_woutsq : g_wqkvsq;

    __shared__ uint4 As[3][128 * 4];
    __shared__ uint4 Bs[3][128 * 4];

    int tid = threadIdx.x;
    int warp = tid >> 5, lane = tid & 31;
    int wm = warp >> 1, wn = warp & 1;
    int row0 = blockIdx.y * 128, col0 = blockIdx.x * 128;

    float acc[2][8][4];
    #pragma unroll
    for (int mt = 0; mt < 2; mt++)
        #pragma unroll
        for (int nt = 0; nt < 8; nt++)
            #pragma unroll
            for (int e = 0; e < 4; e++) acc[mt][nt][e] = 0.f;

    // hoisted ldmatrix addresses for slab 0; slab s = +s*8192 bytes
    uint32_t adA[2][2], adB[2][4];
    #pragma unroll
    for (int kk = 0; kk < 2; kk++) {
        #pragma unroll
        for (int mt = 0; mt < 2; mt++) {
            int r = wm * 32 + mt * 16 + (lane & 15);
            int kc = kk * 2 + (lane >> 4);
            adA[kk][mt] = smem_u32(&As[0][(r << 2) + (kc ^ ((r >> 1) & 3))]);
        }
        #pragma unroll
        for (int jp = 0; jp < 4; jp++) {
            int r = wn * 64 + jp * 16 + (lane & 15);
            int kc = kk * 2 + (lane >> 4);
            adB[kk][jp] = smem_u32(&Bs[0][(r << 2) + (kc ^ ((r >> 1) & 3))]);
        }
    }

    auto prefetch = [&](int buf, int k0) {
        #pragma unroll
        for (int l = 0; l < 2; l++) {
            int cid = tid + (l << 8);
            int r = cid >> 2, kc = cid & 3;
            int pos = (r << 2) + (kc ^ ((r >> 1) & 3));
            cpasync16(smem_u32(&As[buf][pos]), A + (size_t)(row0 + r) * 512 + k0 + (kc << 3));
            cpasync16(smem_u32(&Bs[buf][pos]), B + (size_t)(col0 + r) * 512 + k0 + (kc << 3));
        }
        cp_commit();
    };

    prefetch(0, 0);
    prefetch(1, 32);
    int buf = 0, nslot = 2;
    #pragma unroll 1
    for (int it = 0; it < 16; it++) {
        cp_wait<1>();
        __syncthreads();
        if (it + 2 < 16) {
            prefetch(nslot, (it + 2) << 5);
            nslot = (nslot == 2) ? 0 : nslot + 1;
        } else {
            cp_commit();              // empty group keeps wait<1> accounting uniform
        }
        uint32_t boff = buf << 13;    // 8192 bytes per slab
        #pragma unroll
        for (int kk = 0; kk < 2; kk++) {
            uint32_t af[2][4];
            #pragma unroll
            for (int mt = 0; mt < 2; mt++)
                ldm_x4(af[mt][0], af[mt][1], af[mt][2], af[mt][3], adA[kk][mt] + boff);
            uint32_t bf[8][2];
            #pragma unroll
            for (int jp = 0; jp < 4; jp++) {
                uint32_t t0, t1, t2, t3;
                ldm_x4(t0, t1, t2, t3, adB[kk][jp] + boff);
                bf[jp*2][0] = t0; bf[jp*2][1] = t2;
                bf[jp*2+1][0] = t1; bf[jp*2+1][1] = t3;
            }
            #pragma unroll
            for (int mt = 0; mt < 2; mt++)
                #pragma unroll
                for (int nt = 0; nt < 8; nt++)
                    mma_bf16(acc[mt][nt][0], acc[mt][nt][1], acc[mt][nt][2], acc[mt][nt][3],
                             af[mt][0], af[mt][1], af[mt][2], af[mt][3],
                             bf[nt][0], bf[nt][1]);
        }
        buf = (buf == 2) ? 0 : buf + 1;
    }

    // epilogue
    int r_base = row0 + wm * 32;
    int c_base = col0 + wn * 64;
    int part = c_base >> 9, h = (c_base >> 6) & 7;   // warp-uniform (64-col tile)

    #pragma unroll
    for (int mt = 0; mt < 2; mt++) {
        int r0e = r_base + mt * 16 + (lane >> 2);
        float aq0 = asq[r0e], aq1 = asq[r0e + 8];
        float sum_a = 0.f, sum_b = 0.f;
        #pragma unroll
        for (int nt = 0; nt < 8; nt++) {
            int c = c_base + nt * 8 + ((lane & 3) << 1);
            float bq0 = bsq[c], bq1 = bsq[c + 1];
            float v00 = sqrtf(fmaxf(fmaf(-2.f, acc[mt][nt][0], aq0 + bq0), 0.f));
            float v01 = sqrtf(fmaxf(fmaf(-2.f, acc[mt][nt][1], aq0 + bq1), 0.f));
            float v10 = sqrtf(fmaxf(fmaf(-2.f, acc[mt][nt][2], aq1 + bq0), 0.f));
            float v11 = sqrtf(fmaxf(fmaf(-2.f, acc[mt][nt][3], aq1 + bq1), 0.f));
            if (mode) {
                *(float2*)&Cout[(size_t)r0e * DDIM + c]       = make_float2(v00, v01);
                *(float2*)&Cout[(size_t)(r0e + 8) * DDIM + c] = make_float2(v10, v11);
            } else {
                __nv_bfloat162 p0 = __floats2bfloat162_rn(v00, v01);
                __nv_bfloat162 p1 = __floats2bfloat162_rn(v10, v11);
                int dh = c & 63;
                __nv_bfloat16* dst = (part == 0) ? g_Qb : (part == 1) ? g_Kb : g_Vb;
                int bb = r0e >> 11, n = r0e & 2047;
                size_t i0 = (((size_t)(bb * HHEADS + h)) * NTOK + n) * DHD + dh;
                *(__nv_bfloat162*)&dst[i0]           = p0;
                *(__nv_bfloat162*)&dst[i0 + 8 * DHD] = p1;
                if (part < 2) {
                    float2 f0 = __bfloat1622float2(p0);
                    float2 f1 = __bfloat1622float2(p1);
                    sum_a += f0.x*f0.x + f0.y*f0.y;
                    sum_b += f1.x*f1.x + f1.y*f1.y;
                }
            }
        }
        if (mode == 0 && part < 2) {
            sum_a += __shfl_xor_sync(0xffffffffu, sum_a, 1);
            sum_a += __shfl_xor_sync(0xffffffffu, sum_a, 2);
            sum_b += __shfl_xor_sync(0xffffffffu, sum_b, 1);
            sum_b += __shfl_xor_sync(0xffffffffu, sum_b, 2);
            if ((lane & 3) == 0) {
                float* dq = part ? g_ksq : g_qsq;
                int bb = r0e >> 11, n = r0e & 2047;
                size_t i = ((size_t)(bb * HHEADS + h)) * NTOK + n;
                dq[i] = sum_a * CBR;           // pre-scaled for flash
                dq[i + 8] = sum_b * CBR;
            }
        }
    }
}

// ---------------- fused flash attention (bf16 mma, scalar softmax) ---------
// logits = C2R*(q.k) - qsqs_i - ksqs_j <= 0 (qsqs/ksqs CBR-prescaled).
#define FL_SMEM ((128*9 + 3*576*2) * 16 + 3*64*4)

__global__ __launch_bounds__(256, 2) void flash_mma()
{
    extern __shared__ uint4 fsm[];
    uint4* Qs = fsm;                 // [128][9]
    uint4* Ks = Qs + 128 * 9;        // [3][64][9]
    uint4* Vs = Ks + 3 * 576;        // [3][64][9]
    float* ksq_s = (float*)(Vs + 3 * 576);  // [3][64]

    int tid = threadIdx.x, warp = tid >> 5, lane = tid & 31;
    int bh = blockIdx.y;
    int b = bh >> 3, h = bh & 7;
    int n0 = blockIdx.x * 128;

    const __nv_bfloat16* Qb = g_Qb + (size_t)bh * NTOK * DHD;
    const __nv_bfloat16* Kb = g_Kb + (size_t)bh * NTOK * DHD;
    const __nv_bfloat16* Vb = g_Vb + (size_t)bh * NTOK * DHD;
    const float* ksqb = g_ksq + (size_t)bh * NTOK;

    auto prefetch = [&](int buf, int j0) {
        #pragma unroll
        for (int l = 0; l < 2; l++) {
            int cid = tid + (l << 8);
            int r = cid >> 3, kc = cid & 7;
            cpasync16(smem_u32(&Ks[buf * 576 + r * 9 + kc]), Kb + (size_t)(j0 + r) * 64 + (kc << 3));
            cpasync16(smem_u32(&Vs[buf * 576 + r * 9 + kc]), Vb + (size_t)(j0 + r) * 64 + (kc << 3));
        }
        if (tid < 16) cpasync16(smem_u32(&ksq_s[buf * 64 + tid * 4]), ksqb + j0 + tid * 4);
        cp_commit();
    };

    prefetch(0, 0);
    prefetch(1, 64);

    int ra = n0 + warp * 16 + (lane >> 2);
    float qa_a = g_qsq[(size_t)bh * NTOK + ra];        // CBR-prescaled
    float qa_b = g_qsq[(size_t)bh * NTOK + ra + 8];

    #pragma unroll
    for (int l = 0; l < 4; l++) {
        int cid = tid + (l << 8);
        int r = cid >> 3, kc = cid & 7;
        Qs[r * 9 + kc] = *(const uint4*)(Qb + (size_t)(n0 + r) * 64 + (kc << 3));
    }
    __syncthreads();
    uint32_t qf[4][4];
    #pragma unroll
    for (int ks = 0; ks < 4; ks++) {
        int r = warp * 16 + (lane & 15);
        int kc = ks * 2 + (lane >> 4);
        ldm_x4(qf[ks][0], qf[ks][1], qf[ks][2], qf[ks][3], smem_u32(&Qs[r * 9 + kc]));
    }

    // hoisted ldmatrix bases (slab 0); slab offset cb, k-chunk offsets added
    uint32_t adK[4], adV[4];
    #pragma unroll
    for (int jp = 0; jp < 4; jp++) {
        int r = jp * 16 + (lane & 15);
        adK[jp] = smem_u32(&Ks[r * 9]) + ((lane >> 4) << 4);
        adV[jp] = smem_u32(&Vs[r * 9]) + ((lane >> 4) << 4);
    }

    float o[8][4];
    #pragma unroll
    for (int nt = 0; nt < 8; nt++)
        #pragma unroll
        for (int e = 0; e < 4; e++) o[nt][e] = 0.f;
    float l_a = 0.f, l_b = 0.f;

    int nslot = 2;
    uint32_t cb = 0;                        // compute slab byte offset
    #pragma unroll 1
    for (int kt = 0; kt < 32; kt++) {
        cp_wait<1>();
        __syncthreads();
        if (kt + 2 < 32) {
            prefetch(nslot, (kt + 2) * 64);
            nslot = (nslot == 2) ? 0 : nslot + 1;
        } else {
            cp_commit();              // empty group: uniform wait accounting
        }
        const float* kq = (const float*)((const char*)ksq_s + (cb >> 5) - ((cb >> 5) & 255) + ((cb / 9216) << 8));
        // NOTE: simpler & safe: recompute from slab index
        kq = ksq_s + (cb / 9216) * 64;

        // S = Q K^T
        float s[8][4];
        #pragma unroll
        for (int nt = 0; nt < 8; nt++)
            #pragma unroll
            for (int e = 0; e < 4; e++) s[nt][e] = 0.f;
        #pragma unroll
        for (int ks = 0; ks < 4; ks++) {
            uint32_t bfK[8][2];
            #pragma unroll
            for (int jp = 0; jp < 4; jp++) {
                uint32_t t0, t1, t2, t3;
                ldm_x4(t0, t1, t2, t3, adK[jp] + cb + (ks << 5));
                bfK[jp*2][0] = t0; bfK[jp*2][1] = t2;
                bfK[jp*2+1][0] = t1; bfK[jp*2+1][1] = t3;
            }
            #pragma unroll
            for (int nt = 0; nt < 8; nt++)
                mma_bf16(s[nt][0], s[nt][1], s[nt][2], s[nt][3],
                         qf[ks][0], qf[ks][1], qf[ks][2], qf[ks][3],
                         bfK[nt][0], bfK[nt][1]);
        }

        // scalar softmax numerators (proven path); logit <= 0, no max pass
        uint32_t ph[8][2];
        #pragma unroll
        for (int nt = 0; nt < 8; nt++) {
            int cc = nt * 8 + ((lane & 3) << 1);
            float2 kv = *(float2*)&kq[cc];            // CBR-prescaled ksq pair
            float p0 = exp2_fast(fmaf(s[nt][0], C2R, -(kv.x + qa_a)));
            float p1 = exp2_fast(fmaf(s[nt][1], C2R, -(kv.y + qa_a)));
            float p2 = exp2_fast(fmaf(s[nt][2], C2R, -(kv.x + qa_b)));
            float p3 = exp2_fast(fmaf(s[nt][3], C2R, -(kv.y + qa_b)));
            l_a += p0 + p1; l_b += p2 + p3;
            ph[nt][0] = pack_bf16x2(p0, p1);
            ph[nt][1] = pack_bf16x2(p2, p3);
        }

        // O += P V
        #pragma unroll
        for (int kj = 0; kj < 4; kj++) {
            #pragma unroll
            for (int dp = 0; dp < 4; dp++) {
                uint32_t t0, t1, t2, t3;
                ldm_x4_t(t0, t1, t2, t3, adV[kj] + cb + (dp << 5));
                mma_bf16(o[dp*2][0], o[dp*2][1], o[dp*2][2], o[dp*2][3],
                         ph[2*kj][0], ph[2*kj][1], ph[2*kj+1][0], ph[2*kj+1][1],
                         t0, t1);
                mma_bf16(o[dp*2+1][0], o[dp*2+1][1], o[dp*2+1][2], o[dp*2+1][3],
                         ph[2*kj][0], ph[2*kj][1], ph[2*kj+1][0], ph[2*kj+1][1],
                         t2, t3);
            }
        }
        cb = (cb == 18432) ? 0 : cb + 9216;
    }

    l_a += __shfl_xor_sync(0xffffffffu, l_a, 1);
    l_a += __shfl_xor_sync(0xffffffffu, l_a, 2);
    l_b += __shfl_xor_sync(0xffffffffu, l_b, 1);
    l_b += __shfl_xor_sync(0xffffffffu, l_b, 2);
    float inv_a = 1.f / l_a, inv_b = 1.f / l_b;
    size_t base_a = ((size_t)(b * NTOK) + ra) * DDIM + h * DHD;
    #pragma unroll
    for (int nt = 0; nt < 8; nt++) {
        int d = nt * 8 + ((lane & 3) << 1);
        *(__nv_bfloat162*)&g_Ob[base_a + d] =
            __floats2bfloat162_rn(o[nt][0] * inv_a, o[nt][1] * inv_a);
        *(__nv_bfloat162*)&g_Ob[base_a + 8 * DDIM + d] =
            __floats2bfloat162_rn(o[nt][2] * inv_b, o[nt][3] * inv_b);
    }
}

// ---------------- launch ---------------------------------------------------
extern "C" void kernel_launch(void* const* d_in, const int* in_sizes, int n_in,
                              void* d_out, int out_size)
{
    const float *x = nullptr, *w_qkv = nullptr, *w_out = nullptr;
    for (int i = 0; i < n_in; i++) {
        if (in_sizes[i] == M_ROWS * DDIM)        x     = (const float*)d_in[i];
        else if (in_sizes[i] == QKV_COLS * DDIM) w_qkv = (const float*)d_in[i];
        else if (in_sizes[i] == DDIM * DDIM)     w_out = (const float*)d_in[i];
    }
    float* out = (float*)d_out;

    static bool attr_set = false;
    if (!attr_set) {
        cudaFuncSetAttribute(flash_mma,
            cudaFuncAttributeMaxDynamicSharedMemorySize, FL_SMEM);
        attr_set = true;
    }

    // merged convert + row norms for x, w_qkv, w_out (1 launch)
    cvt_rowsq_all<<<(M_ROWS + QKV_COLS + DDIM) / 8, 256>>>(x, w_qkv, w_out);

    dim3 g1(QKV_COLS / 128, M_ROWS / 128);
    dist_gemm_mma<<<g1, 256>>>(nullptr, 0);

    dim3 gf(NTOK / 128, BBATCH * HHEADS);
    flash_mma<<<gf, 256, FL_SMEM>>>();

    rowsq_o<<<M_ROWS / 8, 256>>>();

    dim3 g3(DDIM / 128, M_ROWS / 128);
    dist_gemm_mma<<<g3, 256>>>(out, 1);
}